// round 2
// baseline (speedup 1.0000x reference)
#include <cuda_runtime.h>
#include <cuda_bf16.h>
#include <math.h>

// Problem constants
#define B_ 2
#define T_ 2048
#define C_ 1024
#define H_ 16
#define N_ 64
#define ROWS_ (B_*T_)            // 4096
#define ELEMS_ (ROWS_*C_)        // 4194304

// ---------------- scratch (device globals; no cudaMalloc allowed) ----------
__device__ float g_xq [ELEMS_];
__device__ float g_xk [ELEMS_];
__device__ float g_xv [ELEMS_];
__device__ float g_xv0[ELEMS_];
__device__ float g_q  [ELEMS_];
__device__ float g_k  [ELEMS_];
__device__ float g_v  [ELEMS_];
__device__ float g_vf [ELEMS_];
__device__ float g_deltas[(size_t)ROWS_*4*C_];   // [4096, 4096]
__device__ float g_ew  [ELEMS_];
__device__ float g_gate[ELEMS_];
__device__ float g_yscan[ELEMS_];
__device__ float g_yfin [ELEMS_];
__device__ __nv_bfloat16 g_sq[ELEMS_];
__device__ __nv_bfloat16 g_sk[ELEMS_];
__device__ __nv_bfloat16 g_sv[ELEMS_];
__device__ __nv_bfloat16 g_sa[ELEMS_];   // z = -kk
__device__ __nv_bfloat16 g_sb[ELEMS_];   // b = kk*a

// ---------------- kernel 1: token shift + mixes ----------------------------
__global__ void prep_kernel(const float* __restrict__ x,
                            const float* __restrict__ x0,
                            const float* __restrict__ dx0,
                            const float* __restrict__ mq,
                            const float* __restrict__ mk,
                            const float* __restrict__ mv)
{
    int idx = blockIdx.x * blockDim.x + threadIdx.x;
    if (idx >= ELEMS_) return;
    int c   = idx & (C_ - 1);
    int row = idx >> 10;          // C_ = 1024
    int t   = row & (T_ - 1);
    float xc = x[idx];
    float xp = (t == 0) ? 0.f : x[idx - C_];
    float dx = xp - xc;
    g_xq [idx] = xc + dx * mq[c];
    g_xk [idx] = xc + dx * mk[c];
    g_xv [idx] = xc + dx * mv[c];
    g_xv0[idx] = x0[idx] + dx0[idx] * mv[c];
}

// ---------------- kernel 2: fp32 SIMT GEMM, C[M,N] = A[M,K] * op(B) --------
// B_KN=false: Bm is [N,K] row-major (W case, C = A @ W^T)
// B_KN=true : Bm is [K,N] row-major (miss case, C = A @ Bm)
// EPI=true  : C = Res + A*op(B)
template<bool B_KN, bool EPI>
__global__ __launch_bounds__(256, 2)
void gemm128(const float* __restrict__ A, int lda,
             const float* __restrict__ Bm, int ldb,
             const float* __restrict__ Res,
             float* __restrict__ Cout,
             int M, int N, int K)
{
    constexpr int BM = 128, BN = 128, BK = 8;
    __shared__ float As[2][BK][BM];
    __shared__ float Bs[2][BK][BN];

    const int tid = threadIdx.x;
    const int bm = blockIdx.y * BM;
    const int bn = blockIdx.x * BN;
    const int tx = tid & 15;
    const int ty = tid >> 4;

    // loaders
    const int am  = tid >> 1;           // 0..127
    const int ak  = (tid & 1) * 4;      // 0 or 4
    const int bnn = tid >> 1;           // NK path: n index 0..127
    const int bkk = (tid & 1) * 4;      // NK path: k offset
    const int bkr = tid >> 5;           // KN path: k row 0..7
    const int bn4 = (tid & 31) * 4;     // KN path: n offset

    float4 aR, bR;

    // prologue load tile 0
    aR = *(const float4*)(A + (size_t)(bm + am) * lda + 0 + ak);
    if (B_KN) bR = *(const float4*)(Bm + (size_t)(0 + bkr) * ldb + bn + bn4);
    else      bR = *(const float4*)(Bm + (size_t)(bn + bnn) * ldb + 0 + bkk);

    As[0][ak+0][am] = aR.x; As[0][ak+1][am] = aR.y;
    As[0][ak+2][am] = aR.z; As[0][ak+3][am] = aR.w;
    if (B_KN) { *(float4*)&Bs[0][bkr][bn4] = bR; }
    else {
        Bs[0][bkk+0][bnn] = bR.x; Bs[0][bkk+1][bnn] = bR.y;
        Bs[0][bkk+2][bnn] = bR.z; Bs[0][bkk+3][bnn] = bR.w;
    }
    __syncthreads();

    float acc[8][8];
#pragma unroll
    for (int i = 0; i < 8; i++)
#pragma unroll
        for (int j = 0; j < 8; j++) acc[i][j] = 0.f;

    const int nk = K / BK;
    for (int kt = 0; kt < nk; kt++) {
        const int buf = kt & 1;
        if (kt + 1 < nk) {
            const int k0 = (kt + 1) * BK;
            aR = *(const float4*)(A + (size_t)(bm + am) * lda + k0 + ak);
            if (B_KN) bR = *(const float4*)(Bm + (size_t)(k0 + bkr) * ldb + bn + bn4);
            else      bR = *(const float4*)(Bm + (size_t)(bn + bnn) * ldb + k0 + bkk);
        }
#pragma unroll
        for (int kk = 0; kk < BK; kk++) {
            float a[8], b[8];
            *(float4*)&a[0] = *(const float4*)&As[buf][kk][ty * 4];
            *(float4*)&a[4] = *(const float4*)&As[buf][kk][64 + ty * 4];
            *(float4*)&b[0] = *(const float4*)&Bs[buf][kk][tx * 4];
            *(float4*)&b[4] = *(const float4*)&Bs[buf][kk][64 + tx * 4];
#pragma unroll
            for (int i = 0; i < 8; i++)
#pragma unroll
                for (int j = 0; j < 8; j++)
                    acc[i][j] = fmaf(a[i], b[j], acc[i][j]);
        }
        if (kt + 1 < nk) {
            const int nb = buf ^ 1;
            As[nb][ak+0][am] = aR.x; As[nb][ak+1][am] = aR.y;
            As[nb][ak+2][am] = aR.z; As[nb][ak+3][am] = aR.w;
            if (B_KN) { *(float4*)&Bs[nb][bkr][bn4] = bR; }
            else {
                Bs[nb][bkk+0][bnn] = bR.x; Bs[nb][bkk+1][bnn] = bR.y;
                Bs[nb][bkk+2][bnn] = bR.z; Bs[nb][bkk+3][bnn] = bR.w;
            }
        }
        __syncthreads();
    }

#pragma unroll
    for (int i = 0; i < 8; i++) {
        const int r = bm + ((i < 4) ? (ty * 4 + i) : (64 + ty * 4 + i - 4));
        size_t off0 = (size_t)r * N + bn + tx * 4;
        size_t off1 = off0 + 64;
        float4 v0 = make_float4(acc[i][0], acc[i][1], acc[i][2], acc[i][3]);
        float4 v1 = make_float4(acc[i][4], acc[i][5], acc[i][6], acc[i][7]);
        if (EPI) {
            float4 r0 = *(const float4*)(Res + off0);
            float4 r1 = *(const float4*)(Res + off1);
            v0.x += r0.x; v0.y += r0.y; v0.z += r0.z; v0.w += r0.w;
            v1.x += r1.x; v1.y += r1.y; v1.z += r1.z; v1.w += r1.w;
        }
        *(float4*)(Cout + off0) = v0;
        *(float4*)(Cout + off1) = v1;
    }
}

// ---------------- kernel 3: per-channel post ops + bf16 rounding -----------
// one warp per (row, head); lane handles channels 2*lane, 2*lane+1
__global__ void post_kernel(const float* __restrict__ w0,
                            const float* __restrict__ v0p,
                            const float* __restrict__ a0p)
{
    const int gh   = blockIdx.x * 8 + (threadIdx.x >> 5); // (row*H + h)
    const int lane = threadIdx.x & 31;
    const int i = gh >> 4;
    const int h = gh & 15;
    const int c0 = h * 64 + lane * 2;
    const size_t base  = (size_t)i * C_ + c0;
    const size_t dbase = (size_t)i * (4 * C_) + c0;

    float k0 = g_k[base], k1 = g_k[base + 1];
    float np = k0 * k0 + k1 * k1;
#pragma unroll
    for (int off = 16; off; off >>= 1)
        np += __shfl_xor_sync(0xffffffffu, np, off);
    float norm = fmaxf(sqrtf(np), 1e-12f);
    float inv = 1.f / norm;

#pragma unroll
    for (int u = 0; u < 2; u++) {
        const size_t cidx = base + u;
        const int    cch  = c0 + u;
        const float  kx   = u ? k1 : k0;

        // w path
        float wlin = w0[cch] + g_deltas[dbase + u];
        float xx = -wlin;
        float sp = (xx > 20.f) ? xx : log1pf(expf(xx));
        float lnw  = -sp - 0.5f;
        float logw = -expf(lnw);
        __nv_bfloat16 wb = __float2bfloat16(logw);
        g_ew[cidx] = expf(__bfloat162float(wb));

        // v path
        float vd = g_deltas[dbase + 1024 + u];
        float sv = 1.f / (1.f + expf(-(v0p[cch] + vd)));
        float vv = g_v[cidx], vf = g_vf[cidx];
        float vnew = vv + (vf - vv) * sv;
        g_sv[cidx] = __float2bfloat16(vnew);

        // a, gate
        float ad = g_deltas[dbase + 2048 + u];
        float a  = 1.f / (1.f + expf(-(a0p[cch] + ad)));
        float gd = g_deltas[dbase + 3072 + u];
        g_gate[cidx] = 1.f + gd;

        // kk / k / z / b / q
        float kk = kx * inv;
        g_sk[cidx] = __float2bfloat16(kx * a);
        g_sa[cidx] = __float2bfloat16(-kk);
        g_sb[cidx] = __float2bfloat16(kk * a);
        g_sq[cidx] = __float2bfloat16(g_q[cidx]);
    }
}

// ---------------- kernel 4: RWKV7 scan -------------------------------------
// grid (B*H, 8); blockDim 256. warp w handles state row v = rg*8 + w.
// lane holds state columns 2*lane, 2*lane+1.
__global__ void scan_kernel()
{
    const int bh = blockIdx.x;          // b*H + h
    const int rg = blockIdx.y;          // 0..7
    const int b = bh >> 4, h = bh & 15;
    const int wid  = threadIdx.x >> 5;
    const int lane = threadIdx.x & 31;
    const int vrow = rg * 8 + wid;

    size_t idx  = (size_t)(b * T_) * C_ + h * 64 + lane * 2;
    size_t vidx = (size_t)(b * T_) * C_ + h * 64 + vrow;

    float s0 = 0.f, s1 = 0.f;

    for (int t = 0; t < T_; t++) {
        float2 qv = __bfloat1622float2(*(const __nv_bfloat162*)(g_sq + idx));
        float2 kv = __bfloat1622float2(*(const __nv_bfloat162*)(g_sk + idx));
        float2 av = __bfloat1622float2(*(const __nv_bfloat162*)(g_sa + idx));
        float2 bv = __bfloat1622float2(*(const __nv_bfloat162*)(g_sb + idx));
        float2 ew = *(const float2*)(g_ew + idx);
        float  vv = __bfloat162float(g_sv[vidx]);

        float t0 = s0 * ew.x;
        float t1 = s1 * ew.y;
        float r_sa = fmaf(s0, av.x, s1 * av.y);
        float r_eq = fmaf(t0, qv.x, t1 * qv.y);
        float r_bq = fmaf(bv.x, qv.x, bv.y * qv.y);
        float r_kq = fmaf(kv.x, qv.x, kv.y * qv.y);

#pragma unroll
        for (int off = 16; off; off >>= 1) {
            r_sa += __shfl_xor_sync(0xffffffffu, r_sa, off);
            r_eq += __shfl_xor_sync(0xffffffffu, r_eq, off);
            r_bq += __shfl_xor_sync(0xffffffffu, r_bq, off);
            r_kq += __shfl_xor_sync(0xffffffffu, r_kq, off);
        }

        s0 = fmaf(r_sa, bv.x, fmaf(vv, kv.x, t0));
        s1 = fmaf(r_sa, bv.y, fmaf(vv, kv.y, t1));

        if (lane == 0)
            g_yscan[vidx] = fmaf(r_sa, r_bq, fmaf(vv, r_kq, r_eq));

        idx  += C_;
        vidx += C_;
    }
}

// ---------------- kernel 5: y corrections ----------------------------------
__global__ void ycorr_kernel(const float* __restrict__ x,
                             const float* __restrict__ r_k)
{
    const int gh   = blockIdx.x * 8 + (threadIdx.x >> 5);
    const int lane = threadIdx.x & 31;
    const int i = gh >> 4, h = gh & 15;
    const size_t base = (size_t)i * C_ + h * 64 + lane * 2;

    float x0v = x[base], x1v = x[base + 1];
    float v0v = __bfloat162float(g_sv[base]);
    float v1v = __bfloat162float(g_sv[base + 1]);

    float xs = x0v * x0v + x1v * x1v;
    float vs = v0v * v0v + v1v * v1v;
#pragma unroll
    for (int off = 16; off; off >>= 1) {
        xs += __shfl_xor_sync(0xffffffffu, xs, off);
        vs += __shfl_xor_sync(0xffffffffu, vs, off);
    }
    float xnorm = sqrtf(xs);
    float vnorm = sqrtf(vs);
    float un = 1.f - xnorm / (vnorm + 1e-12f);

    float rk0 = r_k[h * 64 + lane * 2];
    float rk1 = r_k[h * 64 + lane * 2 + 1];
    float u0 = un / (1.f + expf(-rk0));
    float u1 = un / (1.f + expf(-rk1));

    const float scale = 0.125f;  // N^-0.5 = 1/8
    g_yfin[base]     = (g_yscan[base]     * scale + v0v * u0) * g_gate[base];
    g_yfin[base + 1] = (g_yscan[base + 1] * scale + v1v * u1) * g_gate[base + 1];
}

// ---------------- launch ----------------------------------------------------
extern "C" void kernel_launch(void* const* d_in, const int* in_sizes, int n_in,
                              void* d_out, int out_size)
{
    const float* residual = (const float*)d_in[0];
    const float* x        = (const float*)d_in[1];
    const float* x0       = (const float*)d_in[2];
    const float* dx0      = (const float*)d_in[3];
    const float* Wq       = (const float*)d_in[4];
    const float* Wk       = (const float*)d_in[5];
    const float* Wv       = (const float*)d_in[6];
    const float* Wproj    = (const float*)d_in[7];
    const float* x_q      = (const float*)d_in[8];
    const float* x_k      = (const float*)d_in[9];
    const float* x_v      = (const float*)d_in[10];
    const float* v0       = (const float*)d_in[11];
    const float* w0       = (const float*)d_in[12];
    const float* a0       = (const float*)d_in[13];
    const float* miss     = (const float*)d_in[14];
    const float* r_k      = (const float*)d_in[15];
    float* out = (float*)d_out;

    float *pxq, *pxk, *pxv, *pxv0, *pq, *pk, *pv, *pvf, *pdel, *pyfin;
    cudaGetSymbolAddress((void**)&pxq,  g_xq);
    cudaGetSymbolAddress((void**)&pxk,  g_xk);
    cudaGetSymbolAddress((void**)&pxv,  g_xv);
    cudaGetSymbolAddress((void**)&pxv0, g_xv0);
    cudaGetSymbolAddress((void**)&pq,   g_q);
    cudaGetSymbolAddress((void**)&pk,   g_k);
    cudaGetSymbolAddress((void**)&pv,   g_v);
    cudaGetSymbolAddress((void**)&pvf,  g_vf);
    cudaGetSymbolAddress((void**)&pdel, g_deltas);
    cudaGetSymbolAddress((void**)&pyfin,g_yfin);

    // 1. prep
    prep_kernel<<<ELEMS_ / 256, 256>>>(x, x0, dx0, x_q, x_k, x_v);

    // 2. projections: C = A @ W^T  (M=4096, N=1024, K=1024)
    dim3 gP(C_ / 128, ROWS_ / 128);     // (8, 32)
    gemm128<false, false><<<gP, 256>>>(pxq,  C_, Wq, C_, nullptr, pq,  ROWS_, C_, C_);
    gemm128<false, false><<<gP, 256>>>(pxk,  C_, Wk, C_, nullptr, pk,  ROWS_, C_, C_);
    gemm128<false, false><<<gP, 256>>>(pxv,  C_, Wv, C_, nullptr, pv,  ROWS_, C_, C_);
    gemm128<false, false><<<gP, 256>>>(pxv0, C_, Wv, C_, nullptr, pvf, ROWS_, C_, C_);

    // 3. deltas = x[:, :128] @ miss   (M=4096, N=4096, K=128)
    dim3 gD(4 * C_ / 128, ROWS_ / 128); // (32, 32)
    gemm128<true, false><<<gD, 256>>>(x, C_, miss, 4 * C_, nullptr, pdel,
                                      ROWS_, 4 * C_, 128);

    // 4. post ops + bf16 rounding
    post_kernel<<<ROWS_ * H_ / 8, 256>>>(w0, v0, a0);

    // 5. scan
    scan_kernel<<<dim3(B_ * H_, 8), 256>>>();

    // 6. corrections + gate
    ycorr_kernel<<<ROWS_ * H_ / 8, 256>>>(x, r_k);

    // 7. out = residual + yfin @ Wproj^T
    gemm128<false, true><<<gP, 256>>>(pyfin, C_, Wproj, C_, residual, out,
                                      ROWS_, C_, C_);
}

// round 3
// speedup vs baseline: 1.3881x; 1.3881x over previous
#include <cuda_runtime.h>
#include <cuda_bf16.h>
#include <math.h>

// Problem constants
#define B_ 2
#define T_ 2048
#define C_ 1024
#define H_ 16
#define N_ 64
#define ROWS_ (B_*T_)            // 4096
#define ELEMS_ (ROWS_*C_)        // 4194304

// ---------------- scratch (device globals; no cudaMalloc allowed) ----------
__device__ float g_xq [ELEMS_];
__device__ float g_xk [ELEMS_];
__device__ float g_xv [ELEMS_];
__device__ float g_xv0[ELEMS_];
__device__ float g_q  [ELEMS_];
__device__ float g_k  [ELEMS_];
__device__ float g_v  [ELEMS_];
__device__ float g_vf [ELEMS_];
__device__ float g_deltas[(size_t)ROWS_*4*C_];   // [4096, 4096]
__device__ float g_ew  [ELEMS_];
__device__ float g_gate[ELEMS_];
__device__ float g_yscan[ELEMS_];
__device__ float g_yfin [ELEMS_];
__device__ float g_rbq [ROWS_*H_];   // precomputed b.q per (row, head)
__device__ float g_rkq [ROWS_*H_];   // precomputed k.q per (row, head)
__device__ __nv_bfloat16 g_sq[ELEMS_];
__device__ __nv_bfloat16 g_sk[ELEMS_];
__device__ __nv_bfloat16 g_sv[ELEMS_];
__device__ __nv_bfloat16 g_sa[ELEMS_];   // z = -kk
__device__ __nv_bfloat16 g_sb[ELEMS_];   // b = kk*a

// ---------------- kernel 1: token shift + mixes ----------------------------
__global__ void prep_kernel(const float* __restrict__ x,
                            const float* __restrict__ x0,
                            const float* __restrict__ dx0,
                            const float* __restrict__ mq,
                            const float* __restrict__ mk,
                            const float* __restrict__ mv)
{
    int idx = blockIdx.x * blockDim.x + threadIdx.x;
    if (idx >= ELEMS_) return;
    int c   = idx & (C_ - 1);
    int row = idx >> 10;          // C_ = 1024
    int t   = row & (T_ - 1);
    float xc = x[idx];
    float xp = (t == 0) ? 0.f : x[idx - C_];
    float dx = xp - xc;
    g_xq [idx] = xc + dx * mq[c];
    g_xk [idx] = xc + dx * mk[c];
    g_xv [idx] = xc + dx * mv[c];
    g_xv0[idx] = x0[idx] + dx0[idx] * mv[c];
}

// ---------------- kernel 2: fp32 SIMT GEMM, C[M,N] = A[M,K] * op(B) --------
template<bool B_KN, bool EPI>
__global__ __launch_bounds__(256, 2)
void gemm128(const float* __restrict__ A, int lda,
             const float* __restrict__ Bm, int ldb,
             const float* __restrict__ Res,
             float* __restrict__ Cout,
             int M, int N, int K)
{
    constexpr int BM = 128, BN = 128, BK = 8;
    __shared__ float As[2][BK][BM];
    __shared__ float Bs[2][BK][BN];

    const int tid = threadIdx.x;
    const int bm = blockIdx.y * BM;
    const int bn = blockIdx.x * BN;
    const int tx = tid & 15;
    const int ty = tid >> 4;

    const int am  = tid >> 1;
    const int ak  = (tid & 1) * 4;
    const int bnn = tid >> 1;
    const int bkk = (tid & 1) * 4;
    const int bkr = tid >> 5;
    const int bn4 = (tid & 31) * 4;

    float4 aR, bR;

    aR = *(const float4*)(A + (size_t)(bm + am) * lda + 0 + ak);
    if (B_KN) bR = *(const float4*)(Bm + (size_t)(0 + bkr) * ldb + bn + bn4);
    else      bR = *(const float4*)(Bm + (size_t)(bn + bnn) * ldb + 0 + bkk);

    As[0][ak+0][am] = aR.x; As[0][ak+1][am] = aR.y;
    As[0][ak+2][am] = aR.z; As[0][ak+3][am] = aR.w;
    if (B_KN) { *(float4*)&Bs[0][bkr][bn4] = bR; }
    else {
        Bs[0][bkk+0][bnn] = bR.x; Bs[0][bkk+1][bnn] = bR.y;
        Bs[0][bkk+2][bnn] = bR.z; Bs[0][bkk+3][bnn] = bR.w;
    }
    __syncthreads();

    float acc[8][8];
#pragma unroll
    for (int i = 0; i < 8; i++)
#pragma unroll
        for (int j = 0; j < 8; j++) acc[i][j] = 0.f;

    const int nk = K / BK;
    for (int kt = 0; kt < nk; kt++) {
        const int buf = kt & 1;
        if (kt + 1 < nk) {
            const int k0 = (kt + 1) * BK;
            aR = *(const float4*)(A + (size_t)(bm + am) * lda + k0 + ak);
            if (B_KN) bR = *(const float4*)(Bm + (size_t)(k0 + bkr) * ldb + bn + bn4);
            else      bR = *(const float4*)(Bm + (size_t)(bn + bnn) * ldb + k0 + bkk);
        }
#pragma unroll
        for (int kk = 0; kk < BK; kk++) {
            float a[8], b[8];
            *(float4*)&a[0] = *(const float4*)&As[buf][kk][ty * 4];
            *(float4*)&a[4] = *(const float4*)&As[buf][kk][64 + ty * 4];
            *(float4*)&b[0] = *(const float4*)&Bs[buf][kk][tx * 4];
            *(float4*)&b[4] = *(const float4*)&Bs[buf][kk][64 + tx * 4];
#pragma unroll
            for (int i = 0; i < 8; i++)
#pragma unroll
                for (int j = 0; j < 8; j++)
                    acc[i][j] = fmaf(a[i], b[j], acc[i][j]);
        }
        if (kt + 1 < nk) {
            const int nb = buf ^ 1;
            As[nb][ak+0][am] = aR.x; As[nb][ak+1][am] = aR.y;
            As[nb][ak+2][am] = aR.z; As[nb][ak+3][am] = aR.w;
            if (B_KN) { *(float4*)&Bs[nb][bkr][bn4] = bR; }
            else {
                Bs[nb][bkk+0][bnn] = bR.x; Bs[nb][bkk+1][bnn] = bR.y;
                Bs[nb][bkk+2][bnn] = bR.z; Bs[nb][bkk+3][bnn] = bR.w;
            }
        }
        __syncthreads();
    }

#pragma unroll
    for (int i = 0; i < 8; i++) {
        const int r = bm + ((i < 4) ? (ty * 4 + i) : (64 + ty * 4 + i - 4));
        size_t off0 = (size_t)r * N + bn + tx * 4;
        size_t off1 = off0 + 64;
        float4 v0 = make_float4(acc[i][0], acc[i][1], acc[i][2], acc[i][3]);
        float4 v1 = make_float4(acc[i][4], acc[i][5], acc[i][6], acc[i][7]);
        if (EPI) {
            float4 r0 = *(const float4*)(Res + off0);
            float4 r1 = *(const float4*)(Res + off1);
            v0.x += r0.x; v0.y += r0.y; v0.z += r0.z; v0.w += r0.w;
            v1.x += r1.x; v1.y += r1.y; v1.z += r1.z; v1.w += r1.w;
        }
        *(float4*)(Cout + off0) = v0;
        *(float4*)(Cout + off1) = v1;
    }
}

// ---------------- kernel 3: per-channel post ops + bf16 rounding -----------
// one warp per (row, head); lane handles channels 2*lane, 2*lane+1.
// Also precomputes the state-independent scan scalars r_bq = b.q, r_kq = k.q.
__global__ void post_kernel(const float* __restrict__ w0,
                            const float* __restrict__ v0p,
                            const float* __restrict__ a0p)
{
    const int gh   = blockIdx.x * 8 + (threadIdx.x >> 5); // (row*H + h)
    const int lane = threadIdx.x & 31;
    const int i = gh >> 4;
    const int h = gh & 15;
    const int c0 = h * 64 + lane * 2;
    const size_t base  = (size_t)i * C_ + c0;
    const size_t dbase = (size_t)i * (4 * C_) + c0;

    float k0 = g_k[base], k1 = g_k[base + 1];
    float np = k0 * k0 + k1 * k1;
#pragma unroll
    for (int off = 16; off; off >>= 1)
        np += __shfl_xor_sync(0xffffffffu, np, off);
    float norm = fmaxf(sqrtf(np), 1e-12f);
    float inv = 1.f / norm;

    float qbf[2], kbf[2], bbf[2];

#pragma unroll
    for (int u = 0; u < 2; u++) {
        const size_t cidx = base + u;
        const int    cch  = c0 + u;
        const float  kx   = u ? k1 : k0;

        // w path
        float wlin = w0[cch] + g_deltas[dbase + u];
        float xx = -wlin;
        float sp = (xx > 20.f) ? xx : log1pf(expf(xx));
        float lnw  = -sp - 0.5f;
        float logw = -expf(lnw);
        __nv_bfloat16 wb = __float2bfloat16(logw);
        g_ew[cidx] = expf(__bfloat162float(wb));

        // v path
        float vd = g_deltas[dbase + 1024 + u];
        float sv = 1.f / (1.f + expf(-(v0p[cch] + vd)));
        float vv = g_v[cidx], vf = g_vf[cidx];
        float vnew = vv + (vf - vv) * sv;
        g_sv[cidx] = __float2bfloat16(vnew);

        // a, gate
        float ad = g_deltas[dbase + 2048 + u];
        float a  = 1.f / (1.f + expf(-(a0p[cch] + ad)));
        float gd = g_deltas[dbase + 3072 + u];
        g_gate[cidx] = 1.f + gd;

        // kk / k / z / b / q  (bf16-rounded, matching reference)
        float kk = kx * inv;
        __nv_bfloat16 kb16 = __float2bfloat16(kx * a);
        __nv_bfloat16 ab16 = __float2bfloat16(-kk);
        __nv_bfloat16 bb16 = __float2bfloat16(kk * a);
        __nv_bfloat16 qb16 = __float2bfloat16(g_q[cidx]);
        g_sk[cidx] = kb16;
        g_sa[cidx] = ab16;
        g_sb[cidx] = bb16;
        g_sq[cidx] = qb16;
        kbf[u] = __bfloat162float(kb16);
        bbf[u] = __bfloat162float(bb16);
        qbf[u] = __bfloat162float(qb16);
    }

    // state-independent scan scalars: r_bq = sum_j b_j q_j, r_kq = sum_j k_j q_j
    float rbq = fmaf(qbf[0], bbf[0], qbf[1] * bbf[1]);
    float rkq = fmaf(qbf[0], kbf[0], qbf[1] * kbf[1]);
#pragma unroll
    for (int off = 16; off; off >>= 1) {
        rbq += __shfl_xor_sync(0xffffffffu, rbq, off);
        rkq += __shfl_xor_sync(0xffffffffu, rkq, off);
    }
    if (lane == 0) {
        g_rbq[gh] = rbq;
        g_rkq[gh] = rkq;
    }
}

// ---------------- kernel 4: RWKV7 scan -------------------------------------
// grid (B*H = 32, 8); blockDim 128 (4 warps).
// Each warp handles TWO value rows: lanes 0-15 -> row (by*8 + wid*2),
// lanes 16-31 -> row (by*8 + wid*2 + 1). Each lane holds 4 state columns
// c0..c0+3 with c0 = (lane&15)*4. Reductions are 4-stage half-warp
// butterflies (only r_sa and r_eq are state-dependent; b.q and k.q were
// precomputed in post_kernel).
__global__ __launch_bounds__(128, 8)
void scan_kernel()
{
    const int bh = blockIdx.x;          // b*H + h
    const int b = bh >> 4, h = bh & 15;
    const int wid  = threadIdx.x >> 5;  // 0..3
    const int lane = threadIdx.x & 31;
    const int half = lane >> 4;
    const int c0   = (lane & 15) * 4;
    const int vrow = blockIdx.y * 8 + wid * 2 + half;

    size_t idx  = (size_t)(b * T_) * C_ + h * 64 + c0;
    size_t vidx = (size_t)(b * T_) * C_ + h * 64 + vrow;
    size_t ridx = (size_t)(b * T_) * H_ + h;

    float s0 = 0.f, s1 = 0.f, s2 = 0.f, s3 = 0.f;

    // prefetched operands for the current step
    float4 ew = *(const float4*)(g_ew + idx);
    uint2 qu = *(const uint2*)(g_sq + idx);
    uint2 ku = *(const uint2*)(g_sk + idx);
    uint2 au = *(const uint2*)(g_sa + idx);
    uint2 bu = *(const uint2*)(g_sb + idx);
    float vv  = __bfloat162float(g_sv[vidx]);
    float rbq = g_rbq[ridx];
    float rkq = g_rkq[ridx];

    for (int t = 0; t < T_; t++) {
        // unpack current operands
        float2 q01 = __bfloat1622float2(*(const __nv_bfloat162*)&qu.x);
        float2 q23 = __bfloat1622float2(*(const __nv_bfloat162*)&qu.y);
        float2 k01 = __bfloat1622float2(*(const __nv_bfloat162*)&ku.x);
        float2 k23 = __bfloat1622float2(*(const __nv_bfloat162*)&ku.y);
        float2 a01 = __bfloat1622float2(*(const __nv_bfloat162*)&au.x);
        float2 a23 = __bfloat1622float2(*(const __nv_bfloat162*)&au.y);
        float2 b01 = __bfloat1622float2(*(const __nv_bfloat162*)&bu.x);
        float2 b23 = __bfloat1622float2(*(const __nv_bfloat162*)&bu.y);
        float4 ewc = ew;
        float  vvc = vv, rbqc = rbq, rkqc = rkq;
        size_t vidxc = vidx;

        // prefetch next step (independent of state; hides latency behind shfl)
        if (t + 1 < T_) {
            idx += C_; vidx += C_; ridx += H_;
            ew = *(const float4*)(g_ew + idx);
            qu = *(const uint2*)(g_sq + idx);
            ku = *(const uint2*)(g_sk + idx);
            au = *(const uint2*)(g_sa + idx);
            bu = *(const uint2*)(g_sb + idx);
            vv  = __bfloat162float(g_sv[vidx]);
            rbq = g_rbq[ridx];
            rkq = g_rkq[ridx];
        }

        float t0 = s0 * ewc.x;
        float t1 = s1 * ewc.y;
        float t2 = s2 * ewc.z;
        float t3 = s3 * ewc.w;

        float r_sa = fmaf(s0, a01.x, s1 * a01.y) + fmaf(s2, a23.x, s3 * a23.y);
        float r_eq = fmaf(t0, q01.x, t1 * q01.y) + fmaf(t2, q23.x, t3 * q23.y);

#pragma unroll
        for (int off = 8; off; off >>= 1) {
            r_sa += __shfl_xor_sync(0xffffffffu, r_sa, off);
            r_eq += __shfl_xor_sync(0xffffffffu, r_eq, off);
        }

        s0 = fmaf(r_sa, b01.x, fmaf(vvc, k01.x, t0));
        s1 = fmaf(r_sa, b01.y, fmaf(vvc, k01.y, t1));
        s2 = fmaf(r_sa, b23.x, fmaf(vvc, k23.x, t2));
        s3 = fmaf(r_sa, b23.y, fmaf(vvc, k23.y, t3));

        if ((lane & 15) == 0)
            g_yscan[vidxc] = fmaf(r_sa, rbqc, fmaf(vvc, rkqc, r_eq));
    }
}

// ---------------- kernel 5: y corrections ----------------------------------
__global__ void ycorr_kernel(const float* __restrict__ x,
                             const float* __restrict__ r_k)
{
    const int gh   = blockIdx.x * 8 + (threadIdx.x >> 5);
    const int lane = threadIdx.x & 31;
    const int i = gh >> 4, h = gh & 15;
    const size_t base = (size_t)i * C_ + h * 64 + lane * 2;

    float x0v = x[base], x1v = x[base + 1];
    float v0v = __bfloat162float(g_sv[base]);
    float v1v = __bfloat162float(g_sv[base + 1]);

    float xs = x0v * x0v + x1v * x1v;
    float vs = v0v * v0v + v1v * v1v;
#pragma unroll
    for (int off = 16; off; off >>= 1) {
        xs += __shfl_xor_sync(0xffffffffu, xs, off);
        vs += __shfl_xor_sync(0xffffffffu, vs, off);
    }
    float xnorm = sqrtf(xs);
    float vnorm = sqrtf(vs);
    float un = 1.f - xnorm / (vnorm + 1e-12f);

    float rk0 = r_k[h * 64 + lane * 2];
    float rk1 = r_k[h * 64 + lane * 2 + 1];
    float u0 = un / (1.f + expf(-rk0));
    float u1 = un / (1.f + expf(-rk1));

    const float scale = 0.125f;  // N^-0.5 = 1/8
    g_yfin[base]     = (g_yscan[base]     * scale + v0v * u0) * g_gate[base];
    g_yfin[base + 1] = (g_yscan[base + 1] * scale + v1v * u1) * g_gate[base + 1];
}

// ---------------- launch ----------------------------------------------------
extern "C" void kernel_launch(void* const* d_in, const int* in_sizes, int n_in,
                              void* d_out, int out_size)
{
    const float* residual = (const float*)d_in[0];
    const float* x        = (const float*)d_in[1];
    const float* x0       = (const float*)d_in[2];
    const float* dx0      = (const float*)d_in[3];
    const float* Wq       = (const float*)d_in[4];
    const float* Wk       = (const float*)d_in[5];
    const float* Wv       = (const float*)d_in[6];
    const float* Wproj    = (const float*)d_in[7];
    const float* x_q      = (const float*)d_in[8];
    const float* x_k      = (const float*)d_in[9];
    const float* x_v      = (const float*)d_in[10];
    const float* v0       = (const float*)d_in[11];
    const float* w0       = (const float*)d_in[12];
    const float* a0       = (const float*)d_in[13];
    const float* miss     = (const float*)d_in[14];
    const float* r_k      = (const float*)d_in[15];
    float* out = (float*)d_out;

    float *pxq, *pxk, *pxv, *pxv0, *pq, *pk, *pv, *pvf, *pdel, *pyfin;
    cudaGetSymbolAddress((void**)&pxq,  g_xq);
    cudaGetSymbolAddress((void**)&pxk,  g_xk);
    cudaGetSymbolAddress((void**)&pxv,  g_xv);
    cudaGetSymbolAddress((void**)&pxv0, g_xv0);
    cudaGetSymbolAddress((void**)&pq,   g_q);
    cudaGetSymbolAddress((void**)&pk,   g_k);
    cudaGetSymbolAddress((void**)&pv,   g_v);
    cudaGetSymbolAddress((void**)&pvf,  g_vf);
    cudaGetSymbolAddress((void**)&pdel, g_deltas);
    cudaGetSymbolAddress((void**)&pyfin,g_yfin);

    // 1. prep
    prep_kernel<<<ELEMS_ / 256, 256>>>(x, x0, dx0, x_q, x_k, x_v);

    // 2. projections: C = A @ W^T  (M=4096, N=1024, K=1024)
    dim3 gP(C_ / 128, ROWS_ / 128);     // (8, 32)
    gemm128<false, false><<<gP, 256>>>(pxq,  C_, Wq, C_, nullptr, pq,  ROWS_, C_, C_);
    gemm128<false, false><<<gP, 256>>>(pxk,  C_, Wk, C_, nullptr, pk,  ROWS_, C_, C_);
    gemm128<false, false><<<gP, 256>>>(pxv,  C_, Wv, C_, nullptr, pv,  ROWS_, C_, C_);
    gemm128<false, false><<<gP, 256>>>(pxv0, C_, Wv, C_, nullptr, pvf, ROWS_, C_, C_);

    // 3. deltas = x[:, :128] @ miss   (M=4096, N=4096, K=128)
    dim3 gD(4 * C_ / 128, ROWS_ / 128); // (32, 32)
    gemm128<true, false><<<gD, 256>>>(x, C_, miss, 4 * C_, nullptr, pdel,
                                      ROWS_, 4 * C_, 128);

    // 4. post ops + bf16 rounding + precomputed scan scalars
    post_kernel<<<ROWS_ * H_ / 8, 256>>>(w0, v0, a0);

    // 5. scan (2 value-rows per warp, half-warp butterflies)
    scan_kernel<<<dim3(B_ * H_, 8), 128>>>();

    // 6. corrections + gate
    ycorr_kernel<<<ROWS_ * H_ / 8, 256>>>(x, r_k);

    // 7. out = residual + yfin @ Wproj^T
    gemm128<false, true><<<gP, 256>>>(pyfin, C_, Wproj, C_, residual, out,
                                      ROWS_, C_, C_);
}

// round 4
// speedup vs baseline: 2.0389x; 1.4688x over previous
#include <cuda_runtime.h>
#include <cuda_bf16.h>
#include <math.h>

// Problem constants
#define B_ 2
#define T_ 2048
#define C_ 1024
#define H_ 16
#define N_ 64
#define ROWS_ (B_*T_)            // 4096
#define ELEMS_ (ROWS_*C_)        // 4194304

// ---------------- scratch (device globals; no cudaMalloc allowed) ----------
__device__ float g_xq [ELEMS_];
__device__ float g_xk [ELEMS_];
__device__ float g_xv [ELEMS_];
__device__ float g_xv0[ELEMS_];
__device__ float g_q  [ELEMS_];
__device__ float g_k  [ELEMS_];
__device__ float g_v  [ELEMS_];
__device__ float g_vf [ELEMS_];
__device__ float g_deltas[(size_t)ROWS_*4*C_];   // [4096, 4096]
__device__ float g_ew  [ELEMS_];
__device__ float g_gate[ELEMS_];
__device__ float g_yscan[ELEMS_];
__device__ float g_yfin [ELEMS_];
__device__ float g_rbq [ROWS_*H_];   // precomputed b.q per (row, head)
__device__ float g_rkq [ROWS_*H_];   // precomputed k.q per (row, head)
__device__ __nv_bfloat16 g_sv[ELEMS_];
// packed scan operands: per (row, head, li 0..15): {q01,q23,k01,k23} and {a01,a23,b01,b23}
__device__ uint4 g_pqk[(size_t)ROWS_*H_*16];
__device__ uint4 g_pab[(size_t)ROWS_*H_*16];

// ---------------- kernel 1: token shift + mixes ----------------------------
__global__ void prep_kernel(const float* __restrict__ x,
                            const float* __restrict__ x0,
                            const float* __restrict__ dx0,
                            const float* __restrict__ mq,
                            const float* __restrict__ mk,
                            const float* __restrict__ mv)
{
    int idx = blockIdx.x * blockDim.x + threadIdx.x;
    if (idx >= ELEMS_) return;
    int c   = idx & (C_ - 1);
    int row = idx >> 10;          // C_ = 1024
    int t   = row & (T_ - 1);
    float xc = x[idx];
    float xp = (t == 0) ? 0.f : x[idx - C_];
    float dx = xp - xc;
    g_xq [idx] = xc + dx * mq[c];
    g_xk [idx] = xc + dx * mk[c];
    g_xv [idx] = xc + dx * mv[c];
    g_xv0[idx] = x0[idx] + dx0[idx] * mv[c];
}

// ---------------- kernel 2: fp32 SIMT GEMM, C[M,N] = A[M,K] * op(B) --------
template<bool B_KN, bool EPI>
__global__ __launch_bounds__(256, 2)
void gemm128(const float* __restrict__ A, int lda,
             const float* __restrict__ Bm, int ldb,
             const float* __restrict__ Res,
             float* __restrict__ Cout,
             int M, int N, int K)
{
    constexpr int BM = 128, BN = 128, BK = 8;
    __shared__ float As[2][BK][BM];
    __shared__ float Bs[2][BK][BN];

    const int tid = threadIdx.x;
    const int bm = blockIdx.y * BM;
    const int bn = blockIdx.x * BN;
    const int tx = tid & 15;
    const int ty = tid >> 4;

    const int am  = tid >> 1;
    const int ak  = (tid & 1) * 4;
    const int bnn = tid >> 1;
    const int bkk = (tid & 1) * 4;
    const int bkr = tid >> 5;
    const int bn4 = (tid & 31) * 4;

    float4 aR, bR;

    aR = *(const float4*)(A + (size_t)(bm + am) * lda + 0 + ak);
    if (B_KN) bR = *(const float4*)(Bm + (size_t)(0 + bkr) * ldb + bn + bn4);
    else      bR = *(const float4*)(Bm + (size_t)(bn + bnn) * ldb + 0 + bkk);

    As[0][ak+0][am] = aR.x; As[0][ak+1][am] = aR.y;
    As[0][ak+2][am] = aR.z; As[0][ak+3][am] = aR.w;
    if (B_KN) { *(float4*)&Bs[0][bkr][bn4] = bR; }
    else {
        Bs[0][bkk+0][bnn] = bR.x; Bs[0][bkk+1][bnn] = bR.y;
        Bs[0][bkk+2][bnn] = bR.z; Bs[0][bkk+3][bnn] = bR.w;
    }
    __syncthreads();

    float acc[8][8];
#pragma unroll
    for (int i = 0; i < 8; i++)
#pragma unroll
        for (int j = 0; j < 8; j++) acc[i][j] = 0.f;

    const int nk = K / BK;
    for (int kt = 0; kt < nk; kt++) {
        const int buf = kt & 1;
        if (kt + 1 < nk) {
            const int k0 = (kt + 1) * BK;
            aR = *(const float4*)(A + (size_t)(bm + am) * lda + k0 + ak);
            if (B_KN) bR = *(const float4*)(Bm + (size_t)(k0 + bkr) * ldb + bn + bn4);
            else      bR = *(const float4*)(Bm + (size_t)(bn + bnn) * ldb + k0 + bkk);
        }
#pragma unroll
        for (int kk = 0; kk < BK; kk++) {
            float a[8], b[8];
            *(float4*)&a[0] = *(const float4*)&As[buf][kk][ty * 4];
            *(float4*)&a[4] = *(const float4*)&As[buf][kk][64 + ty * 4];
            *(float4*)&b[0] = *(const float4*)&Bs[buf][kk][tx * 4];
            *(float4*)&b[4] = *(const float4*)&Bs[buf][kk][64 + tx * 4];
#pragma unroll
            for (int i = 0; i < 8; i++)
#pragma unroll
                for (int j = 0; j < 8; j++)
                    acc[i][j] = fmaf(a[i], b[j], acc[i][j]);
        }
        if (kt + 1 < nk) {
            const int nb = buf ^ 1;
            As[nb][ak+0][am] = aR.x; As[nb][ak+1][am] = aR.y;
            As[nb][ak+2][am] = aR.z; As[nb][ak+3][am] = aR.w;
            if (B_KN) { *(float4*)&Bs[nb][bkr][bn4] = bR; }
            else {
                Bs[nb][bkk+0][bnn] = bR.x; Bs[nb][bkk+1][bnn] = bR.y;
                Bs[nb][bkk+2][bnn] = bR.z; Bs[nb][bkk+3][bnn] = bR.w;
            }
        }
        __syncthreads();
    }

#pragma unroll
    for (int i = 0; i < 8; i++) {
        const int r = bm + ((i < 4) ? (ty * 4 + i) : (64 + ty * 4 + i - 4));
        size_t off0 = (size_t)r * N + bn + tx * 4;
        size_t off1 = off0 + 64;
        float4 v0 = make_float4(acc[i][0], acc[i][1], acc[i][2], acc[i][3]);
        float4 v1 = make_float4(acc[i][4], acc[i][5], acc[i][6], acc[i][7]);
        if (EPI) {
            float4 r0 = *(const float4*)(Res + off0);
            float4 r1 = *(const float4*)(Res + off1);
            v0.x += r0.x; v0.y += r0.y; v0.z += r0.z; v0.w += r0.w;
            v1.x += r1.x; v1.y += r1.y; v1.z += r1.z; v1.w += r1.w;
        }
        *(float4*)(Cout + off0) = v0;
        *(float4*)(Cout + off1) = v1;
    }
}

// ---------------- kernel 3: per-channel post ops + packing ------------------
// one warp per (row, head-pair): lanes 0-15 -> head hp*2, lanes 16-31 -> hp*2+1,
// each lane handles 4 channels. Produces packed bf16 operands for the scan and
// the precomputed state-independent scalars r_bq = b.q, r_kq = k.q.
__global__ void post_kernel(const float* __restrict__ w0,
                            const float* __restrict__ v0p,
                            const float* __restrict__ a0p)
{
    const int gw   = blockIdx.x * 8 + (threadIdx.x >> 5); // (row * 8 + hp)
    const int lane = threadIdx.x & 31;
    const int row  = gw >> 3;
    const int hp   = gw & 7;
    const int h    = hp * 2 + (lane >> 4);
    const int li   = lane & 15;
    const int c0   = h * 64 + li * 4;
    const size_t base  = (size_t)row * C_ + c0;
    const size_t dbase = (size_t)row * (4 * C_) + c0;

    float4 kraw = *(const float4*)(g_k + base);
    float np = fmaf(kraw.x, kraw.x, kraw.y * kraw.y)
             + fmaf(kraw.z, kraw.z, kraw.w * kraw.w);
#pragma unroll
    for (int off = 8; off; off >>= 1)
        np += __shfl_xor_sync(0xffffffffu, np, off);
    float inv = 1.f / fmaxf(sqrtf(np), 1e-12f);

    float4 wdel = *(const float4*)(g_deltas + dbase);
    float4 vdel = *(const float4*)(g_deltas + dbase + 1024);
    float4 adel = *(const float4*)(g_deltas + dbase + 2048);
    float4 gdel = *(const float4*)(g_deltas + dbase + 3072);
    float4 w0v  = *(const float4*)(w0  + c0);
    float4 v0v  = *(const float4*)(v0p + c0);
    float4 a0v  = *(const float4*)(a0p + c0);
    float4 vraw = *(const float4*)(g_v  + base);
    float4 vfr  = *(const float4*)(g_vf + base);
    float4 qraw = *(const float4*)(g_q  + base);

    float ews[4], vns[4], qs[4], ks[4], as_[4], bs[4], gs[4];
    const float* wd = &wdel.x; const float* vd = &vdel.x;
    const float* ad = &adel.x; const float* gd = &gdel.x;
    const float* w0a = &w0v.x; const float* v0a = &v0v.x; const float* a0a = &a0v.x;
    const float* kr = &kraw.x; const float* vr = &vraw.x;
    const float* vf = &vfr.x;  const float* qr = &qraw.x;

#pragma unroll
    for (int u = 0; u < 4; u++) {
        // w path
        float xx = -(w0a[u] + wd[u]);
        float sp = (xx > 20.f) ? xx : log1pf(expf(xx));
        float logw = -expf(-sp - 0.5f);
        ews[u] = expf(__bfloat162float(__float2bfloat16(logw)));

        // v path
        float sv = 1.f / (1.f + expf(-(v0a[u] + vd[u])));
        float vnew = vr[u] + (vf[u] - vr[u]) * sv;
        __nv_bfloat16 vb = __float2bfloat16(vnew);
        vns[u] = __bfloat162float(vb);

        // a, gate
        float a = 1.f / (1.f + expf(-(a0a[u] + ad[u])));
        gs[u] = 1.f + gd[u];

        // kk / k / z / b / q (bf16-rounded, matching reference)
        float kk = kr[u] * inv;
        __nv_bfloat16 kb = __float2bfloat16(kr[u] * a);
        __nv_bfloat16 ab = __float2bfloat16(-kk);
        __nv_bfloat16 bb = __float2bfloat16(kk * a);
        __nv_bfloat16 qb = __float2bfloat16(qr[u]);
        ks[u]  = __bfloat162float(kb);
        as_[u] = __bfloat162float(ab);
        bs[u]  = __bfloat162float(bb);
        qs[u]  = __bfloat162float(qb);
    }

    // stores
    *(float4*)(g_ew + base)   = make_float4(ews[0], ews[1], ews[2], ews[3]);
    *(float4*)(g_gate + base) = make_float4(gs[0], gs[1], gs[2], gs[3]);
    {
        __nv_bfloat162 v01 = __floats2bfloat162_rn(vns[0], vns[1]);
        __nv_bfloat162 v23 = __floats2bfloat162_rn(vns[2], vns[3]);
        uint2 vp;
        vp.x = *(const unsigned int*)&v01;
        vp.y = *(const unsigned int*)&v23;
        *(uint2*)(g_sv + base) = vp;
    }
    {
        __nv_bfloat162 q01 = __floats2bfloat162_rn(qs[0], qs[1]);
        __nv_bfloat162 q23 = __floats2bfloat162_rn(qs[2], qs[3]);
        __nv_bfloat162 k01 = __floats2bfloat162_rn(ks[0], ks[1]);
        __nv_bfloat162 k23 = __floats2bfloat162_rn(ks[2], ks[3]);
        __nv_bfloat162 a01 = __floats2bfloat162_rn(as_[0], as_[1]);
        __nv_bfloat162 a23 = __floats2bfloat162_rn(as_[2], as_[3]);
        __nv_bfloat162 b01 = __floats2bfloat162_rn(bs[0], bs[1]);
        __nv_bfloat162 b23 = __floats2bfloat162_rn(bs[2], bs[3]);
        uint4 pqk, pab;
        pqk.x = *(const unsigned int*)&q01; pqk.y = *(const unsigned int*)&q23;
        pqk.z = *(const unsigned int*)&k01; pqk.w = *(const unsigned int*)&k23;
        pab.x = *(const unsigned int*)&a01; pab.y = *(const unsigned int*)&a23;
        pab.z = *(const unsigned int*)&b01; pab.w = *(const unsigned int*)&b23;
        const size_t pidx = ((size_t)row * H_ + h) * 16 + li;
        g_pqk[pidx] = pqk;
        g_pab[pidx] = pab;
    }

    // state-independent scalars
    float rbq = fmaf(qs[0], bs[0], qs[1] * bs[1]) + fmaf(qs[2], bs[2], qs[3] * bs[3]);
    float rkq = fmaf(qs[0], ks[0], qs[1] * ks[1]) + fmaf(qs[2], ks[2], qs[3] * ks[3]);
#pragma unroll
    for (int off = 8; off; off >>= 1) {
        rbq += __shfl_xor_sync(0xffffffffu, rbq, off);
        rkq += __shfl_xor_sync(0xffffffffu, rkq, off);
    }
    if (li == 0) {
        g_rbq[(size_t)row * H_ + h] = rbq;
        g_rkq[(size_t)row * H_ + h] = rkq;
    }
}

// ---------------- kernel 4: RWKV7 scan -------------------------------------
// grid (B*H = 32, 8); blockDim 128 (4 warps). Each warp handles two value rows
// (half-warps of 16 lanes, 4 state columns per lane). 4-deep software pipeline
// covers L2 latency (~260 cyc) with loads issued ~560 cyc ahead.
__global__ __launch_bounds__(128)
void scan_kernel()
{
    const int bh = blockIdx.x;          // b*H + h
    const int b = bh >> 4, h = bh & 15;
    const int wid  = threadIdx.x >> 5;  // 0..3
    const int lane = threadIdx.x & 31;
    const int half = lane >> 4;
    const int li   = lane & 15;
    const int vrow = blockIdx.y * 8 + wid * 2 + half;

    const size_t row0    = (size_t)b * T_;
    const size_t ew_base = row0 * C_ + h * 64 + li * 4;
    const size_t pk_base = (row0 * H_ + h) * 16 + li;
    const size_t v_base  = row0 * C_ + h * 64 + vrow;
    const size_t r_base  = row0 * H_ + h;

    float4 pf_ew[4];
    uint4  pf_qk[4], pf_ab[4];
    float  pf_v[4], pf_rbq[4], pf_rkq[4];

#pragma unroll
    for (int j = 0; j < 4; j++) {
        pf_ew[j] = *(const float4*)(g_ew + ew_base + (size_t)j * C_);
        pf_qk[j] = g_pqk[pk_base + (size_t)j * (H_ * 16)];
        pf_ab[j] = g_pab[pk_base + (size_t)j * (H_ * 16)];
        pf_v[j]  = __bfloat162float(g_sv[v_base + (size_t)j * C_]);
        pf_rbq[j] = g_rbq[r_base + (size_t)j * H_];
        pf_rkq[j] = g_rkq[r_base + (size_t)j * H_];
    }

    float s0 = 0.f, s1 = 0.f, s2 = 0.f, s3 = 0.f;

    for (int t = 0; t < T_; t += 4) {
#pragma unroll
        for (int j = 0; j < 4; j++) {
            // grab current operands
            const float4 ewc = pf_ew[j];
            const uint4  qk  = pf_qk[j];
            const uint4  ab  = pf_ab[j];
            const float  vvc = pf_v[j];
            const float  rbqc = pf_rbq[j];
            const float  rkqc = pf_rkq[j];

            // prefetch step t+4+j (clamped to last step; uniform, harmless)
            int tn = t + 4 + j;
            if (tn > T_ - 1) tn = T_ - 1;
            pf_ew[j] = *(const float4*)(g_ew + ew_base + (size_t)tn * C_);
            pf_qk[j] = g_pqk[pk_base + (size_t)tn * (H_ * 16)];
            pf_ab[j] = g_pab[pk_base + (size_t)tn * (H_ * 16)];
            pf_v[j]  = __bfloat162float(g_sv[v_base + (size_t)tn * C_]);
            pf_rbq[j] = g_rbq[r_base + (size_t)tn * H_];
            pf_rkq[j] = g_rkq[r_base + (size_t)tn * H_];

            // unpack
            float2 q01 = __bfloat1622float2(*(const __nv_bfloat162*)&qk.x);
            float2 q23 = __bfloat1622float2(*(const __nv_bfloat162*)&qk.y);
            float2 k01 = __bfloat1622float2(*(const __nv_bfloat162*)&qk.z);
            float2 k23 = __bfloat1622float2(*(const __nv_bfloat162*)&qk.w);
            float2 a01 = __bfloat1622float2(*(const __nv_bfloat162*)&ab.x);
            float2 a23 = __bfloat1622float2(*(const __nv_bfloat162*)&ab.y);
            float2 b01 = __bfloat1622float2(*(const __nv_bfloat162*)&ab.z);
            float2 b23 = __bfloat1622float2(*(const __nv_bfloat162*)&ab.w);

            float t0 = s0 * ewc.x;
            float t1 = s1 * ewc.y;
            float t2 = s2 * ewc.z;
            float t3 = s3 * ewc.w;

            float r_sa = fmaf(s0, a01.x, s1 * a01.y) + fmaf(s2, a23.x, s3 * a23.y);
            float r_eq = fmaf(t0, q01.x, t1 * q01.y) + fmaf(t2, q23.x, t3 * q23.y);

#pragma unroll
            for (int off = 8; off; off >>= 1) {
                r_sa += __shfl_xor_sync(0xffffffffu, r_sa, off);
                r_eq += __shfl_xor_sync(0xffffffffu, r_eq, off);
            }

            s0 = fmaf(r_sa, b01.x, fmaf(vvc, k01.x, t0));
            s1 = fmaf(r_sa, b01.y, fmaf(vvc, k01.y, t1));
            s2 = fmaf(r_sa, b23.x, fmaf(vvc, k23.x, t2));
            s3 = fmaf(r_sa, b23.y, fmaf(vvc, k23.y, t3));

            if (li == 0)
                g_yscan[v_base + (size_t)(t + j) * C_] =
                    fmaf(r_sa, rbqc, fmaf(vvc, rkqc, r_eq));
        }
    }
}

// ---------------- kernel 5: y corrections ----------------------------------
__global__ void ycorr_kernel(const float* __restrict__ x,
                             const float* __restrict__ r_k)
{
    const int gh   = blockIdx.x * 8 + (threadIdx.x >> 5);
    const int lane = threadIdx.x & 31;
    const int i = gh >> 4, h = gh & 15;
    const size_t base = (size_t)i * C_ + h * 64 + lane * 2;

    float x0v = x[base], x1v = x[base + 1];
    float v0v = __bfloat162float(g_sv[base]);
    float v1v = __bfloat162float(g_sv[base + 1]);

    float xs = x0v * x0v + x1v * x1v;
    float vs = v0v * v0v + v1v * v1v;
#pragma unroll
    for (int off = 16; off; off >>= 1) {
        xs += __shfl_xor_sync(0xffffffffu, xs, off);
        vs += __shfl_xor_sync(0xffffffffu, vs, off);
    }
    float xnorm = sqrtf(xs);
    float vnorm = sqrtf(vs);
    float un = 1.f - xnorm / (vnorm + 1e-12f);

    float rk0 = r_k[h * 64 + lane * 2];
    float rk1 = r_k[h * 64 + lane * 2 + 1];
    float u0 = un / (1.f + expf(-rk0));
    float u1 = un / (1.f + expf(-rk1));

    const float scale = 0.125f;  // N^-0.5 = 1/8
    g_yfin[base]     = (g_yscan[base]     * scale + v0v * u0) * g_gate[base];
    g_yfin[base + 1] = (g_yscan[base + 1] * scale + v1v * u1) * g_gate[base + 1];
}

// ---------------- launch ----------------------------------------------------
extern "C" void kernel_launch(void* const* d_in, const int* in_sizes, int n_in,
                              void* d_out, int out_size)
{
    const float* residual = (const float*)d_in[0];
    const float* x        = (const float*)d_in[1];
    const float* x0       = (const float*)d_in[2];
    const float* dx0      = (const float*)d_in[3];
    const float* Wq       = (const float*)d_in[4];
    const float* Wk       = (const float*)d_in[5];
    const float* Wv       = (const float*)d_in[6];
    const float* Wproj    = (const float*)d_in[7];
    const float* x_q      = (const float*)d_in[8];
    const float* x_k      = (const float*)d_in[9];
    const float* x_v      = (const float*)d_in[10];
    const float* v0       = (const float*)d_in[11];
    const float* w0       = (const float*)d_in[12];
    const float* a0       = (const float*)d_in[13];
    const float* miss     = (const float*)d_in[14];
    const float* r_k      = (const float*)d_in[15];
    float* out = (float*)d_out;

    float *pxq, *pxk, *pxv, *pxv0, *pq, *pk, *pv, *pvf, *pdel, *pyfin;
    cudaGetSymbolAddress((void**)&pxq,  g_xq);
    cudaGetSymbolAddress((void**)&pxk,  g_xk);
    cudaGetSymbolAddress((void**)&pxv,  g_xv);
    cudaGetSymbolAddress((void**)&pxv0, g_xv0);
    cudaGetSymbolAddress((void**)&pq,   g_q);
    cudaGetSymbolAddress((void**)&pk,   g_k);
    cudaGetSymbolAddress((void**)&pv,   g_v);
    cudaGetSymbolAddress((void**)&pvf,  g_vf);
    cudaGetSymbolAddress((void**)&pdel, g_deltas);
    cudaGetSymbolAddress((void**)&pyfin,g_yfin);

    // 1. prep
    prep_kernel<<<ELEMS_ / 256, 256>>>(x, x0, dx0, x_q, x_k, x_v);

    // 2. projections: C = A @ W^T  (M=4096, N=1024, K=1024)
    dim3 gP(C_ / 128, ROWS_ / 128);     // (8, 32)
    gemm128<false, false><<<gP, 256>>>(pxq,  C_, Wq, C_, nullptr, pq,  ROWS_, C_, C_);
    gemm128<false, false><<<gP, 256>>>(pxk,  C_, Wk, C_, nullptr, pk,  ROWS_, C_, C_);
    gemm128<false, false><<<gP, 256>>>(pxv,  C_, Wv, C_, nullptr, pv,  ROWS_, C_, C_);
    gemm128<false, false><<<gP, 256>>>(pxv0, C_, Wv, C_, nullptr, pvf, ROWS_, C_, C_);

    // 3. deltas = x[:, :128] @ miss   (M=4096, N=4096, K=128)
    dim3 gD(4 * C_ / 128, ROWS_ / 128); // (32, 32)
    gemm128<true, false><<<gD, 256>>>(x, C_, miss, 4 * C_, nullptr, pdel,
                                      ROWS_, 4 * C_, 128);

    // 4. post ops + bf16 rounding + packing + precomputed scan scalars
    post_kernel<<<ROWS_ * 8 / 8, 256>>>(w0, v0, a0);

    // 5. scan (packed operands, 4-deep pipeline)
    scan_kernel<<<dim3(B_ * H_, 8), 128>>>();

    // 6. corrections + gate
    ycorr_kernel<<<ROWS_ * H_ / 8, 256>>>(x, r_k);

    // 7. out = residual + yfin @ Wproj^T
    gemm128<false, true><<<gP, 256>>>(pyfin, C_, Wproj, C_, residual, out,
                                      ROWS_, C_, C_);
}

// round 6
// speedup vs baseline: 3.2236x; 1.5810x over previous
#include <cuda_runtime.h>
#include <cuda_bf16.h>
#include <math.h>
#include <stdint.h>

// Problem constants
#define B_ 2
#define T_ 2048
#define C_ 1024
#define H_ 16
#define ROWS_ (B_*T_)            // 4096
#define ELEMS_ (ROWS_*C_)        // 4194304

// ---------------- scratch (device globals; no cudaMalloc allowed) ----------
__device__ float g_q  [ELEMS_];
__device__ float g_k  [ELEMS_];
__device__ float g_v  [ELEMS_];
__device__ float g_vf [ELEMS_];
__device__ float g_deltas[(size_t)ROWS_*4*C_];   // [4096, 4096]
__device__ float g_ew  [ELEMS_];
__device__ float g_gate[ELEMS_];
__device__ float g_yscan[ELEMS_];
__device__ float g_rbq [ROWS_*H_];
__device__ float g_rkq [ROWS_*H_];
__device__ __nv_bfloat16 g_sv[ELEMS_];
__device__ uint4 g_pqk[(size_t)ROWS_*H_*16];
__device__ uint4 g_pab[(size_t)ROWS_*H_*16];

// bf16 hi/lo operand buffers for bf16x3 GEMMs
__device__ __nv_bfloat16 g_xqh[ELEMS_], g_xql[ELEMS_];
__device__ __nv_bfloat16 g_xkh[ELEMS_], g_xkl[ELEMS_];
__device__ __nv_bfloat16 g_xvh[ELEMS_], g_xvl[ELEMS_];
__device__ __nv_bfloat16 g_x0h[ELEMS_], g_x0l[ELEMS_];
__device__ __nv_bfloat16 g_wqh[C_*C_],  g_wql[C_*C_];
__device__ __nv_bfloat16 g_wkh[C_*C_],  g_wkl[C_*C_];
__device__ __nv_bfloat16 g_wvh[C_*C_],  g_wvl[C_*C_];
__device__ __nv_bfloat16 g_wph[C_*C_],  g_wpl[C_*C_];
__device__ __nv_bfloat16 g_xh [ROWS_*128], g_xl [ROWS_*128];
__device__ __nv_bfloat16 g_mth[4*C_*128],  g_mtl[4*C_*128];
__device__ __nv_bfloat16 g_yfh[ELEMS_], g_yfl[ELEMS_];

// ---------------- helpers ----------------------------------------------------
__device__ __forceinline__ uint32_t smem_u32(const void* p) {
    uint32_t a;
    asm("{ .reg .u64 t; cvta.to.shared.u64 t, %1; cvt.u32.u64 %0, t; }"
        : "=r"(a) : "l"(p));
    return a;
}
__device__ __forceinline__ uint32_t lds32(uint32_t addr) {
    uint32_t v;
    asm volatile("ld.shared.b32 %0, [%1];" : "=r"(v) : "r"(addr));
    return v;
}
#define CPA16(dst32, src) \
    asm volatile("cp.async.cg.shared.global [%0], [%1], 16;" \
                 :: "r"(dst32), "l"(src))
#define CPA_COMMIT() asm volatile("cp.async.commit_group;" ::: "memory")
#define CPA_WAIT(n)  asm volatile("cp.async.wait_group %0;" :: "n"(n) : "memory")

__device__ __forceinline__ void mma_bf16(float* c, const uint32_t* a,
                                         const uint32_t* b) {
    asm volatile(
        "mma.sync.aligned.m16n8k16.row.col.f32.bf16.bf16.f32 "
        "{%0,%1,%2,%3}, {%4,%5,%6,%7}, {%8,%9}, {%0,%1,%2,%3};"
        : "+f"(c[0]), "+f"(c[1]), "+f"(c[2]), "+f"(c[3])
        : "r"(a[0]), "r"(a[1]), "r"(a[2]), "r"(a[3]), "r"(b[0]), "r"(b[1]));
}

__device__ __forceinline__ void f2hl(float v, __nv_bfloat16& h, __nv_bfloat16& l) {
    h = __float2bfloat16(v);
    l = __float2bfloat16(v - __bfloat162float(h));
}

// ---------------- conversion kernels ----------------------------------------
__global__ void conv_w4(const float* __restrict__ Wq, const float* __restrict__ Wk,
                        const float* __restrict__ Wv, const float* __restrict__ Wp)
{
    int i = blockIdx.x * blockDim.x + threadIdx.x;  // 0 .. 4*C*C-1
    int sel = i >> 20;                               // C*C = 1M
    int j = i & (C_ * C_ - 1);
    switch (sel) {
        case 0: f2hl(Wq[j], g_wqh[j], g_wql[j]); break;
        case 1: f2hl(Wk[j], g_wkh[j], g_wkl[j]); break;
        case 2: f2hl(Wv[j], g_wvh[j], g_wvl[j]); break;
        default: f2hl(Wp[j], g_wph[j], g_wpl[j]); break;
    }
}

__global__ void conv_xmt(const float* __restrict__ x, const float* __restrict__ miss)
{
    int i = blockIdx.x * blockDim.x + threadIdx.x;  // 0 .. 2*4096*128-1
    if (i < ROWS_ * 128) {
        int row = i >> 7, c = i & 127;
        f2hl(x[(size_t)row * C_ + c], g_xh[i], g_xl[i]);
    } else {
        int j = i - ROWS_ * 128;
        int nrow = j >> 7, k = j & 127;
        f2hl(miss[(size_t)k * (4 * C_) + nrow], g_mth[j], g_mtl[j]);
    }
}

// ---------------- kernel 1: token shift + mixes (emit bf16 hi/lo) ----------
__global__ void prep_kernel(const float* __restrict__ x,
                            const float* __restrict__ x0,
                            const float* __restrict__ dx0,
                            const float* __restrict__ mq,
                            const float* __restrict__ mk,
                            const float* __restrict__ mv)
{
    int idx = blockIdx.x * blockDim.x + threadIdx.x;
    if (idx >= ELEMS_) return;
    int c   = idx & (C_ - 1);
    int row = idx >> 10;
    int t   = row & (T_ - 1);
    float xc = x[idx];
    float xp = (t == 0) ? 0.f : x[idx - C_];
    float dx = xp - xc;
    f2hl(xc + dx * mq[c],            g_xqh[idx], g_xql[idx]);
    f2hl(xc + dx * mk[c],            g_xkh[idx], g_xkl[idx]);
    f2hl(xc + dx * mv[c],            g_xvh[idx], g_xvl[idx]);
    f2hl(x0[idx] + dx0[idx] * mv[c], g_x0h[idx], g_x0l[idx]);
}

// ---------------- kernel 2: mma.sync bf16x3 GEMM -----------------------------
// D[M,N] = (Ah+Al)[M,K] @ (Bh+Bl)[N,K]^T   (K-major row-major operands)
// CTA: 128x128 tile, 256 threads = 8 warps (4x2), warp tile 32x64.
// K-stages of 64, double-buffered smem via cp.async, XOR-swizzled 128B rows.
// Smem layout: stage s (65536B) -> tile t in {Ah,Al,Bh,Bl} (16384B each)
//   -> row (128B) -> chunk ((j ^ (row&7))*16).
#define GSTAGE_ (65536)
#define GSMEM_BYTES (2 * GSTAGE_)

template<bool EPI>
__global__ __launch_bounds__(256)
void gemm_mma(const __nv_bfloat16* __restrict__ Ah, const __nv_bfloat16* __restrict__ Al,
              const __nv_bfloat16* __restrict__ Bh, const __nv_bfloat16* __restrict__ Bl,
              const float* __restrict__ Res, float* __restrict__ Cout,
              int Nn, int K)
{
    extern __shared__ char smem[];
    const uint32_t smem32 = smem_u32(smem);

    const int tid  = threadIdx.x;
    const int wid  = tid >> 5;
    const int lane = tid & 31;
    const int wm   = wid >> 1;        // 0..3
    const int wn   = wid & 1;         // 0..1
    const int qrow = lane >> 2;       // 0..7
    const int sub  = (lane & 3) * 4;  // byte offset within 16B chunk
    const int bm   = blockIdx.y * 128;
    const int bn   = blockIdx.x * 128;
    const int NC   = K >> 6;

    const __nv_bfloat16* gsrc[4] = {Ah, Al, Bh, Bl};
    const int rbase[4] = {bm, bm, bn, bn};

    // issue one K-stage of cp.async copies into buffer s
    auto issue = [&](int ck, int s) {
        const int kcol = ck * 64;
        const uint32_t sb = smem32 + (uint32_t)s * GSTAGE_;
#pragma unroll
        for (int t = 0; t < 4; t++) {
            const __nv_bfloat16* gp = gsrc[t];
            const int rb = rbase[t];
#pragma unroll
            for (int i = 0; i < 4; i++) {
                int id  = tid + i * 256;           // 0..1023
                int row = id >> 3;
                int j   = id & 7;
                uint32_t dst = sb + (uint32_t)t * 16384 + row * 128
                             + ((uint32_t)(j ^ (row & 7)) << 4);
                const void* src = gp + (size_t)(rb + row) * K + kcol + j * 8;
                CPA16(dst, src);
            }
        }
        CPA_COMMIT();
    };

    float acc[2][8][4];
#pragma unroll
    for (int mt = 0; mt < 2; mt++)
#pragma unroll
        for (int nt = 0; nt < 8; nt++)
#pragma unroll
            for (int r = 0; r < 4; r++) acc[mt][nt][r] = 0.f;

    issue(0, 0);
    if (NC > 1) issue(1, 1);

    for (int ck = 0; ck < NC; ck++) {
        if (ck + 1 < NC) { CPA_WAIT(1); } else { CPA_WAIT(0); }
        __syncthreads();

        const uint32_t sb  = smem32 + (uint32_t)(ck & 1) * GSTAGE_;
        const uint32_t ahb = sb;
        const uint32_t alb = sb + 16384;
        const uint32_t bhb = sb + 32768;
        const uint32_t blb = sb + 49152;

#pragma unroll
        for (int ks = 0; ks < 4; ks++) {
            const int c0 = 2 * ks, c1 = 2 * ks + 1;
            uint32_t ahf[2][4], alf[2][4];
#pragma unroll
            for (int mt = 0; mt < 2; mt++) {
                int r0 = wm * 32 + mt * 16 + qrow;
                int r8 = r0 + 8;
                uint32_t o00 = r0 * 128 + ((uint32_t)(c0 ^ (r0 & 7)) << 4) + sub;
                uint32_t o80 = r8 * 128 + ((uint32_t)(c0 ^ (r8 & 7)) << 4) + sub;
                uint32_t o01 = r0 * 128 + ((uint32_t)(c1 ^ (r0 & 7)) << 4) + sub;
                uint32_t o81 = r8 * 128 + ((uint32_t)(c1 ^ (r8 & 7)) << 4) + sub;
                ahf[mt][0] = lds32(ahb + o00);
                ahf[mt][1] = lds32(ahb + o80);
                ahf[mt][2] = lds32(ahb + o01);
                ahf[mt][3] = lds32(ahb + o81);
                alf[mt][0] = lds32(alb + o00);
                alf[mt][1] = lds32(alb + o80);
                alf[mt][2] = lds32(alb + o01);
                alf[mt][3] = lds32(alb + o81);
            }
#pragma unroll
            for (int nt = 0; nt < 8; nt++) {
                int rn = wn * 64 + nt * 8 + qrow;
                uint32_t on0 = rn * 128 + ((uint32_t)(c0 ^ (rn & 7)) << 4) + sub;
                uint32_t on1 = rn * 128 + ((uint32_t)(c1 ^ (rn & 7)) << 4) + sub;
                uint32_t bhf[2], blf[2];
                bhf[0] = lds32(bhb + on0);
                bhf[1] = lds32(bhb + on1);
                blf[0] = lds32(blb + on0);
                blf[1] = lds32(blb + on1);
#pragma unroll
                for (int mt = 0; mt < 2; mt++) {
                    mma_bf16(acc[mt][nt], ahf[mt], bhf);
                    mma_bf16(acc[mt][nt], ahf[mt], blf);
                    mma_bf16(acc[mt][nt], alf[mt], bhf);
                }
            }
        }
        __syncthreads();
        if (ck + 2 < NC) issue(ck + 2, ck & 1);
    }

    // epilogue
#pragma unroll
    for (int mt = 0; mt < 2; mt++) {
#pragma unroll
        for (int nt = 0; nt < 8; nt++) {
            int row = bm + wm * 32 + mt * 16 + qrow;
            int col = bn + wn * 64 + nt * 8 + 2 * (lane & 3);
            size_t o0 = (size_t)row * Nn + col;
            size_t o1 = o0 + 8 * (size_t)Nn;
            float2 v0 = make_float2(acc[mt][nt][0], acc[mt][nt][1]);
            float2 v1 = make_float2(acc[mt][nt][2], acc[mt][nt][3]);
            if (EPI) {
                float2 r0 = *(const float2*)(Res + o0);
                float2 r1 = *(const float2*)(Res + o1);
                v0.x += r0.x; v0.y += r0.y;
                v1.x += r1.x; v1.y += r1.y;
            }
            *(float2*)(Cout + o0) = v0;
            *(float2*)(Cout + o1) = v1;
        }
    }
}

// ---------------- kernel 3: per-channel post ops + packing ------------------
__global__ void post_kernel(const float* __restrict__ w0,
                            const float* __restrict__ v0p,
                            const float* __restrict__ a0p)
{
    const int gw   = blockIdx.x * 8 + (threadIdx.x >> 5); // (row * 8 + hp)
    const int lane = threadIdx.x & 31;
    const int row  = gw >> 3;
    const int hp   = gw & 7;
    const int h    = hp * 2 + (lane >> 4);
    const int li   = lane & 15;
    const int c0   = h * 64 + li * 4;
    const size_t base  = (size_t)row * C_ + c0;
    const size_t dbase = (size_t)row * (4 * C_) + c0;

    float4 kraw = *(const float4*)(g_k + base);
    float np = fmaf(kraw.x, kraw.x, kraw.y * kraw.y)
             + fmaf(kraw.z, kraw.z, kraw.w * kraw.w);
#pragma unroll
    for (int off = 8; off; off >>= 1)
        np += __shfl_xor_sync(0xffffffffu, np, off);
    float inv = 1.f / fmaxf(sqrtf(np), 1e-12f);

    float4 wdel = *(const float4*)(g_deltas + dbase);
    float4 vdel = *(const float4*)(g_deltas + dbase + 1024);
    float4 adel = *(const float4*)(g_deltas + dbase + 2048);
    float4 gdel = *(const float4*)(g_deltas + dbase + 3072);
    float4 w0v  = *(const float4*)(w0  + c0);
    float4 v0v  = *(const float4*)(v0p + c0);
    float4 a0v  = *(const float4*)(a0p + c0);
    float4 vraw = *(const float4*)(g_v  + base);
    float4 vfr  = *(const float4*)(g_vf + base);
    float4 qraw = *(const float4*)(g_q  + base);

    float ews[4], vns[4], qs[4], ks[4], as_[4], bs[4], gs[4];
    const float* wd = &wdel.x; const float* vd = &vdel.x;
    const float* ad = &adel.x; const float* gd = &gdel.x;
    const float* w0a = &w0v.x; const float* v0a = &v0v.x; const float* a0a = &a0v.x;
    const float* kr = &kraw.x; const float* vr = &vraw.x;
    const float* vf = &vfr.x;  const float* qr = &qraw.x;

#pragma unroll
    for (int u = 0; u < 4; u++) {
        float xx = -(w0a[u] + wd[u]);
        float sp = (xx > 20.f) ? xx : log1pf(expf(xx));
        float logw = -expf(-sp - 0.5f);
        ews[u] = expf(__bfloat162float(__float2bfloat16(logw)));

        float sv = 1.f / (1.f + expf(-(v0a[u] + vd[u])));
        float vnew = vr[u] + (vf[u] - vr[u]) * sv;
        vns[u] = __bfloat162float(__float2bfloat16(vnew));

        float a = 1.f / (1.f + expf(-(a0a[u] + ad[u])));
        gs[u] = 1.f + gd[u];

        float kk = kr[u] * inv;
        __nv_bfloat16 kb = __float2bfloat16(kr[u] * a);
        __nv_bfloat16 ab = __float2bfloat16(-kk);
        __nv_bfloat16 bb = __float2bfloat16(kk * a);
        __nv_bfloat16 qb = __float2bfloat16(qr[u]);
        ks[u]  = __bfloat162float(kb);
        as_[u] = __bfloat162float(ab);
        bs[u]  = __bfloat162float(bb);
        qs[u]  = __bfloat162float(qb);
    }

    *(float4*)(g_ew + base)   = make_float4(ews[0], ews[1], ews[2], ews[3]);
    *(float4*)(g_gate + base) = make_float4(gs[0], gs[1], gs[2], gs[3]);
    {
        __nv_bfloat162 v01 = __floats2bfloat162_rn(vns[0], vns[1]);
        __nv_bfloat162 v23 = __floats2bfloat162_rn(vns[2], vns[3]);
        uint2 vp;
        vp.x = *(const unsigned int*)&v01;
        vp.y = *(const unsigned int*)&v23;
        *(uint2*)(g_sv + base) = vp;
    }
    {
        __nv_bfloat162 q01 = __floats2bfloat162_rn(qs[0], qs[1]);
        __nv_bfloat162 q23 = __floats2bfloat162_rn(qs[2], qs[3]);
        __nv_bfloat162 k01 = __floats2bfloat162_rn(ks[0], ks[1]);
        __nv_bfloat162 k23 = __floats2bfloat162_rn(ks[2], ks[3]);
        __nv_bfloat162 a01 = __floats2bfloat162_rn(as_[0], as_[1]);
        __nv_bfloat162 a23 = __floats2bfloat162_rn(as_[2], as_[3]);
        __nv_bfloat162 b01 = __floats2bfloat162_rn(bs[0], bs[1]);
        __nv_bfloat162 b23 = __floats2bfloat162_rn(bs[2], bs[3]);
        uint4 pqk, pab;
        pqk.x = *(const unsigned int*)&q01; pqk.y = *(const unsigned int*)&q23;
        pqk.z = *(const unsigned int*)&k01; pqk.w = *(const unsigned int*)&k23;
        pab.x = *(const unsigned int*)&a01; pab.y = *(const unsigned int*)&a23;
        pab.z = *(const unsigned int*)&b01; pab.w = *(const unsigned int*)&b23;
        const size_t pidx = ((size_t)row * H_ + h) * 16 + li;
        g_pqk[pidx] = pqk;
        g_pab[pidx] = pab;
    }

    float rbq = fmaf(qs[0], bs[0], qs[1] * bs[1]) + fmaf(qs[2], bs[2], qs[3] * bs[3]);
    float rkq = fmaf(qs[0], ks[0], qs[1] * ks[1]) + fmaf(qs[2], ks[2], qs[3] * ks[3]);
#pragma unroll
    for (int off = 8; off; off >>= 1) {
        rbq += __shfl_xor_sync(0xffffffffu, rbq, off);
        rkq += __shfl_xor_sync(0xffffffffu, rkq, off);
    }
    if (li == 0) {
        g_rbq[(size_t)row * H_ + h] = rbq;
        g_rkq[(size_t)row * H_ + h] = rkq;
    }
}

// ---------------- kernel 4: RWKV7 scan -------------------------------------
__global__ __launch_bounds__(128)
void scan_kernel()
{
    const int bh = blockIdx.x;
    const int b = bh >> 4, h = bh & 15;
    const int wid  = threadIdx.x >> 5;
    const int lane = threadIdx.x & 31;
    const int half = lane >> 4;
    const int li   = lane & 15;
    const int vrow = blockIdx.y * 8 + wid * 2 + half;

    const size_t row0    = (size_t)b * T_;
    const size_t ew_base = row0 * C_ + h * 64 + li * 4;
    const size_t pk_base = (row0 * H_ + h) * 16 + li;
    const size_t v_base  = row0 * C_ + h * 64 + vrow;
    const size_t r_base  = row0 * H_ + h;

    float4 pf_ew[4];
    uint4  pf_qk[4], pf_ab[4];
    float  pf_v[4], pf_rbq[4], pf_rkq[4];

#pragma unroll
    for (int j = 0; j < 4; j++) {
        pf_ew[j] = *(const float4*)(g_ew + ew_base + (size_t)j * C_);
        pf_qk[j] = g_pqk[pk_base + (size_t)j * (H_ * 16)];
        pf_ab[j] = g_pab[pk_base + (size_t)j * (H_ * 16)];
        pf_v[j]  = __bfloat162float(g_sv[v_base + (size_t)j * C_]);
        pf_rbq[j] = g_rbq[r_base + (size_t)j * H_];
        pf_rkq[j] = g_rkq[r_base + (size_t)j * H_];
    }

    float s0 = 0.f, s1 = 0.f, s2 = 0.f, s3 = 0.f;

    for (int t = 0; t < T_; t += 4) {
#pragma unroll
        for (int j = 0; j < 4; j++) {
            const float4 ewc = pf_ew[j];
            const uint4  qk  = pf_qk[j];
            const uint4  ab  = pf_ab[j];
            const float  vvc = pf_v[j];
            const float  rbqc = pf_rbq[j];
            const float  rkqc = pf_rkq[j];

            int tn = t + 4 + j;
            if (tn > T_ - 1) tn = T_ - 1;
            pf_ew[j] = *(const float4*)(g_ew + ew_base + (size_t)tn * C_);
            pf_qk[j] = g_pqk[pk_base + (size_t)tn * (H_ * 16)];
            pf_ab[j] = g_pab[pk_base + (size_t)tn * (H_ * 16)];
            pf_v[j]  = __bfloat162float(g_sv[v_base + (size_t)tn * C_]);
            pf_rbq[j] = g_rbq[r_base + (size_t)tn * H_];
            pf_rkq[j] = g_rkq[r_base + (size_t)tn * H_];

            float2 q01 = __bfloat1622float2(*(const __nv_bfloat162*)&qk.x);
            float2 q23 = __bfloat1622float2(*(const __nv_bfloat162*)&qk.y);
            float2 k01 = __bfloat1622float2(*(const __nv_bfloat162*)&qk.z);
            float2 k23 = __bfloat1622float2(*(const __nv_bfloat162*)&qk.w);
            float2 a01 = __bfloat1622float2(*(const __nv_bfloat162*)&ab.x);
            float2 a23 = __bfloat1622float2(*(const __nv_bfloat162*)&ab.y);
            float2 b01 = __bfloat1622float2(*(const __nv_bfloat162*)&ab.z);
            float2 b23 = __bfloat1622float2(*(const __nv_bfloat162*)&ab.w);

            float t0 = s0 * ewc.x;
            float t1 = s1 * ewc.y;
            float t2 = s2 * ewc.z;
            float t3 = s3 * ewc.w;

            float r_sa = fmaf(s0, a01.x, s1 * a01.y) + fmaf(s2, a23.x, s3 * a23.y);
            float r_eq = fmaf(t0, q01.x, t1 * q01.y) + fmaf(t2, q23.x, t3 * q23.y);

#pragma unroll
            for (int off = 8; off; off >>= 1) {
                r_sa += __shfl_xor_sync(0xffffffffu, r_sa, off);
                r_eq += __shfl_xor_sync(0xffffffffu, r_eq, off);
            }

            s0 = fmaf(r_sa, b01.x, fmaf(vvc, k01.x, t0));
            s1 = fmaf(r_sa, b01.y, fmaf(vvc, k01.y, t1));
            s2 = fmaf(r_sa, b23.x, fmaf(vvc, k23.x, t2));
            s3 = fmaf(r_sa, b23.y, fmaf(vvc, k23.y, t3));

            if (li == 0)
                g_yscan[v_base + (size_t)(t + j) * C_] =
                    fmaf(r_sa, rbqc, fmaf(vvc, rkqc, r_eq));
        }
    }
}

// ---------------- kernel 5: y corrections (emit bf16 hi/lo) ----------------
__global__ void ycorr_kernel(const float* __restrict__ x,
                             const float* __restrict__ r_k)
{
    const int gh   = blockIdx.x * 8 + (threadIdx.x >> 5);
    const int lane = threadIdx.x & 31;
    const int i = gh >> 4, h = gh & 15;
    const size_t base = (size_t)i * C_ + h * 64 + lane * 2;

    float x0v = x[base], x1v = x[base + 1];
    float v0v = __bfloat162float(g_sv[base]);
    float v1v = __bfloat162float(g_sv[base + 1]);

    float xs = x0v * x0v + x1v * x1v;
    float vs = v0v * v0v + v1v * v1v;
#pragma unroll
    for (int off = 16; off; off >>= 1) {
        xs += __shfl_xor_sync(0xffffffffu, xs, off);
        vs += __shfl_xor_sync(0xffffffffu, vs, off);
    }
    float xnorm = sqrtf(xs);
    float vnorm = sqrtf(vs);
    float un = 1.f - xnorm / (vnorm + 1e-12f);

    float rk0 = r_k[h * 64 + lane * 2];
    float rk1 = r_k[h * 64 + lane * 2 + 1];
    float u0 = un / (1.f + expf(-rk0));
    float u1 = un / (1.f + expf(-rk1));

    const float scale = 0.125f;
    float y0 = (g_yscan[base]     * scale + v0v * u0) * g_gate[base];
    float y1 = (g_yscan[base + 1] * scale + v1v * u1) * g_gate[base + 1];
    f2hl(y0, g_yfh[base],     g_yfl[base]);
    f2hl(y1, g_yfh[base + 1], g_yfl[base + 1]);
}

// ---------------- launch ----------------------------------------------------
extern "C" void kernel_launch(void* const* d_in, const int* in_sizes, int n_in,
                              void* d_out, int out_size)
{
    const float* residual = (const float*)d_in[0];
    const float* x        = (const float*)d_in[1];
    const float* x0       = (const float*)d_in[2];
    const float* dx0      = (const float*)d_in[3];
    const float* Wq       = (const float*)d_in[4];
    const float* Wk       = (const float*)d_in[5];
    const float* Wv       = (const float*)d_in[6];
    const float* Wproj    = (const float*)d_in[7];
    const float* x_q      = (const float*)d_in[8];
    const float* x_k      = (const float*)d_in[9];
    const float* x_v      = (const float*)d_in[10];
    const float* v0       = (const float*)d_in[11];
    const float* w0       = (const float*)d_in[12];
    const float* a0       = (const float*)d_in[13];
    const float* miss     = (const float*)d_in[14];
    const float* r_k      = (const float*)d_in[15];
    float* out = (float*)d_out;

    __nv_bfloat16 *xqh, *xql, *xkh, *xkl, *xvh, *xvl, *x0h, *x0l;
    __nv_bfloat16 *wqh, *wql, *wkh, *wkl, *wvh, *wvl, *wph, *wpl;
    __nv_bfloat16 *xh, *xl, *mth, *mtl, *yfh, *yfl;
    float *pq, *pk, *pv, *pvf, *pdel;
    cudaGetSymbolAddress((void**)&xqh, g_xqh); cudaGetSymbolAddress((void**)&xql, g_xql);
    cudaGetSymbolAddress((void**)&xkh, g_xkh); cudaGetSymbolAddress((void**)&xkl, g_xkl);
    cudaGetSymbolAddress((void**)&xvh, g_xvh); cudaGetSymbolAddress((void**)&xvl, g_xvl);
    cudaGetSymbolAddress((void**)&x0h, g_x0h); cudaGetSymbolAddress((void**)&x0l, g_x0l);
    cudaGetSymbolAddress((void**)&wqh, g_wqh); cudaGetSymbolAddress((void**)&wql, g_wql);
    cudaGetSymbolAddress((void**)&wkh, g_wkh); cudaGetSymbolAddress((void**)&wkl, g_wkl);
    cudaGetSymbolAddress((void**)&wvh, g_wvh); cudaGetSymbolAddress((void**)&wvl, g_wvl);
    cudaGetSymbolAddress((void**)&wph, g_wph); cudaGetSymbolAddress((void**)&wpl, g_wpl);
    cudaGetSymbolAddress((void**)&xh,  g_xh);  cudaGetSymbolAddress((void**)&xl,  g_xl);
    cudaGetSymbolAddress((void**)&mth, g_mth); cudaGetSymbolAddress((void**)&mtl, g_mtl);
    cudaGetSymbolAddress((void**)&yfh, g_yfh); cudaGetSymbolAddress((void**)&yfl, g_yfl);
    cudaGetSymbolAddress((void**)&pq,  g_q);   cudaGetSymbolAddress((void**)&pk,  g_k);
    cudaGetSymbolAddress((void**)&pv,  g_v);   cudaGetSymbolAddress((void**)&pvf, g_vf);
    cudaGetSymbolAddress((void**)&pdel, g_deltas);

    cudaFuncSetAttribute(gemm_mma<false>, cudaFuncAttributeMaxDynamicSharedMemorySize, GSMEM_BYTES);
    cudaFuncSetAttribute(gemm_mma<true>,  cudaFuncAttributeMaxDynamicSharedMemorySize, GSMEM_BYTES);

    // conversions (independent)
    conv_w4<<<4 * C_ * C_ / 256, 256>>>(Wq, Wk, Wv, Wproj);
    conv_xmt<<<2 * ROWS_ * 128 / 256, 256>>>(x, miss);
    prep_kernel<<<ELEMS_ / 256, 256>>>(x, x0, dx0, x_q, x_k, x_v);

    // projections: [4096,1024] = A @ W^T, K=1024
    dim3 gP(C_ / 128, ROWS_ / 128);     // (8, 32)
    gemm_mma<false><<<gP, 256, GSMEM_BYTES>>>(xqh, xql, wqh, wql, nullptr, pq,  C_, C_);
    gemm_mma<false><<<gP, 256, GSMEM_BYTES>>>(xkh, xkl, wkh, wkl, nullptr, pk,  C_, C_);
    gemm_mma<false><<<gP, 256, GSMEM_BYTES>>>(xvh, xvl, wvh, wvl, nullptr, pv,  C_, C_);
    gemm_mma<false><<<gP, 256, GSMEM_BYTES>>>(x0h, x0l, wvh, wvl, nullptr, pvf, C_, C_);

    // deltas: [4096,4096] = x[:, :128] @ missT^T, K=128
    dim3 gD(4 * C_ / 128, ROWS_ / 128); // (32, 32)
    gemm_mma<false><<<gD, 256, GSMEM_BYTES>>>(xh, xl, mth, mtl, nullptr, pdel, 4 * C_, 128);

    // post ops + packing
    post_kernel<<<ROWS_ * 8 / 8, 256>>>(w0, v0, a0);

    // scan
    scan_kernel<<<dim3(B_ * H_, 8), 128>>>();

    // corrections + gate (emits yfin hi/lo)
    ycorr_kernel<<<ROWS_ * H_ / 8, 256>>>(x, r_k);

    // out = residual + yfin @ Wproj^T
    gemm_mma<true><<<gP, 256, GSMEM_BYTES>>>(yfh, yfl, wph, wpl, residual, out, C_, C_);
}